// round 12
// baseline (speedup 1.0000x reference)
#include <cuda_runtime.h>
#include <cuda_bf16.h>
#include <cuda_fp16.h>
#include <math.h>
#include <stdint.h>

#define DD     1024
#define HH     2048
#define EE     8
#define NTOK   8192
#define KTOP   2
#define NP     (NTOK*KTOP)      // 16384
#define BM     128
#define MAXPAD (NP + EE*BM)     // 17408
#define MAXTILES (MAXPAD/BM)    // 136

#define STRA   80               // A smem row stride (32 fp16 = 64B + 16B pad)
#define TILEA  (128*STRA)       // 10240
#define STRB1  144              // B smem row stride (64 fp16 + pad)
#define TILEW1 (32*STRB1)       // 4608

// ---------------- device scratch ----------------
__device__ float g_pair_w[MAXPAD];
__device__ int   g_slot_tok[MAXPAD];   // slot -> token (-1 = pad)
__device__ int   g_topk_idx[NP];
__device__ float g_topk_val[NP];
__device__ float g_scores[NTOK*EE];
__device__ int   g_counts[EE];
__device__ int   g_cursor[EE];
__device__ int   g_pstart[EE+1];
__device__ int   g_tile_expert[MAXTILES];

__device__ __align__(16) __half g_xg [(size_t)MAXPAD*DD];      // fp16 x (gathered)
__device__ __align__(16) __half g_w1 [(size_t)EE*DD*HH];       // fp16 W1 [E][D][H]
__device__ __align__(16) __half g_w3 [(size_t)EE*DD*HH];
__device__ __align__(16) __half g_w2 [(size_t)EE*HH*DD];       // fp16 W2 [E][H][D]
__device__ __align__(16) __half g_h  [(size_t)MAXPAD*HH];      // fp16 h

// ---------------- PTX helpers (baseline PTX only) ----------------
__device__ __forceinline__ uint32_t smem_u32(const void* p){
    uint32_t a;
    asm("{ .reg .u64 t; cvta.to.shared.u64 t, %1; cvt.u32.u64 %0, t; }" : "=r"(a) : "l"(p));
    return a;
}
__device__ __forceinline__ void cpasync16(uint32_t dst, const void* src){
    asm volatile("cp.async.cg.shared.global [%0], [%1], 16;" :: "r"(dst), "l"(src));
}
#define CP_COMMIT() asm volatile("cp.async.commit_group;" ::: "memory")
#define CP_WAIT2()  asm volatile("cp.async.wait_group 2;" ::: "memory")

__device__ __forceinline__ void ldmx4(uint32_t (&r)[4], uint32_t addr){
    asm volatile("ldmatrix.sync.aligned.m8n8.x4.shared.b16 {%0,%1,%2,%3}, [%4];"
        : "=r"(r[0]), "=r"(r[1]), "=r"(r[2]), "=r"(r[3]) : "r"(addr));
}
__device__ __forceinline__ void ldmx4t(uint32_t (&r)[4], uint32_t addr){
    asm volatile("ldmatrix.sync.aligned.m8n8.x4.trans.shared.b16 {%0,%1,%2,%3}, [%4];"
        : "=r"(r[0]), "=r"(r[1]), "=r"(r[2]), "=r"(r[3]) : "r"(addr));
}
__device__ __forceinline__ void mma16816(float (&c)[4], const uint32_t (&a)[4],
                                         uint32_t b0, uint32_t b1){
    asm volatile(
        "mma.sync.aligned.m16n8k16.row.col.f32.f16.f16.f32 "
        "{%0,%1,%2,%3}, {%4,%5,%6,%7}, {%8,%9}, {%0,%1,%2,%3};"
        : "+f"(c[0]), "+f"(c[1]), "+f"(c[2]), "+f"(c[3])
        : "r"(a[0]), "r"(a[1]), "r"(a[2]), "r"(a[3]), "r"(b0), "r"(b1));
}
__device__ __forceinline__ void redadd2(float* p, float a, float b){
    asm volatile("red.global.add.v2.f32 [%0], {%1, %2};"
        :: "l"(p), "f"(a), "f"(b) : "memory");
}

// ---------------- init: counters + slot_tok pads ----------------
__global__ void init_kernel() {
    int i = blockIdx.x*blockDim.x + threadIdx.x;
    if (i < MAXPAD) g_slot_tok[i] = -1;
    if (i < EE) { g_counts[i] = 0; g_cursor[i] = 0; }
}

// ---------------- zero the output (side stream) ----------------
__global__ void zeroout_kernel(float* __restrict__ out, int n4, int ntail) {
    int i = blockIdx.x*blockDim.x + threadIdx.x;
    if (i < n4) ((float4*)out)[i] = make_float4(0.f,0.f,0.f,0.f);
    if (i < ntail) out[(size_t)n4*4 + i] = 0.f;
}

// ---------------- gating: 4 tokens per warp, Wg staged once per block --------
__global__ void __launch_bounds__(256) gate_kernel(const float* __restrict__ x,
                                                   const float* __restrict__ Wg) {
    __shared__ float sWg[EE*DD];
    for (int i = threadIdx.x; i < EE*DD/4; i += 256)
        ((float4*)sWg)[i] = ((const float4*)Wg)[i];
    __syncthreads();

    int warp = threadIdx.x >> 5;
    int lane = threadIdx.x & 31;

    for (int t = 0; t < 4; t++) {
        int n = blockIdx.x*32 + warp*4 + t;

        const float4* xr = (const float4*)(x + (size_t)n*DD);
        float4 xv[8];
        #pragma unroll
        for (int q = 0; q < 8; q++) xv[q] = xr[lane + q*32];

        float pr[EE];
        #pragma unroll
        for (int e = 0; e < EE; e++) {
            const float4* wr = (const float4*)(sWg + e*DD);
            float p = 0.f;
            #pragma unroll
            for (int q = 0; q < 8; q++) {
                float4 w = wr[lane + q*32];
                p += xv[q].x*w.x + xv[q].y*w.y + xv[q].z*w.z + xv[q].w*w.w;
            }
            #pragma unroll
            for (int off = 16; off; off >>= 1) p += __shfl_xor_sync(0xffffffffu, p, off);
            pr[e] = p;
        }
        float m = pr[0];
        #pragma unroll
        for (int e = 1; e < EE; e++) m = fmaxf(m, pr[e]);
        float s = 0.f;
        #pragma unroll
        for (int e = 0; e < EE; e++) { pr[e] = __expf(pr[e]-m); s += pr[e]; }
        float inv = 1.f/s;
        #pragma unroll
        for (int e = 0; e < EE; e++) pr[e] *= inv;

        int i1 = 0; float v1 = pr[0];
        #pragma unroll
        for (int e = 1; e < EE; e++) if (pr[e] > v1) { v1 = pr[e]; i1 = e; }
        int i2 = -1; float v2 = -1.f;
        #pragma unroll
        for (int e = 0; e < EE; e++) if (e != i1 && pr[e] > v2) { v2 = pr[e]; i2 = e; }

        if (lane == 0) {
            #pragma unroll
            for (int e = 0; e < EE; e++) g_scores[(size_t)n*EE + e] = pr[e];
            g_topk_idx[2*n]   = i1; g_topk_val[2*n]   = v1;
            g_topk_idx[2*n+1] = i2; g_topk_val[2*n+1] = v2;
            atomicAdd(&g_counts[i1], 1);
            atomicAdd(&g_counts[i2], 1);
        }
    }
}

// ---------------- setup (parallel, 1 block) ----------------
__global__ void setup_kernel() {
    __shared__ int ps[EE+1], cnt[EE];
    int tid = threadIdx.x;
    if (tid == 0) {
        int off = 0;
        for (int e = 0; e < EE; e++) {
            ps[e] = off;
            int c = g_counts[e];
            cnt[e] = c;
            off = (off + c + BM - 1)/BM*BM;
        }
        ps[EE] = off;
    }
    __syncthreads();
    if (tid <= EE) g_pstart[tid] = ps[tid];
    if (tid < MAXTILES) {
        int r0 = tid*BM, e = -1;
        #pragma unroll
        for (int ee = 0; ee < EE; ee++)
            if (r0 >= ps[ee] && r0 < ps[ee] + cnt[ee]) e = ee;
        g_tile_expert[tid] = e;
    }
}

// ---------------- fused assign + gather (one warp per TOKEN) ----------------
__global__ void __launch_bounds__(256) assign_gather_kernel(const float* __restrict__ x) {
    int warp = threadIdx.x >> 5;
    int lane = threadIdx.x & 31;
    int n = blockIdx.x*8 + warp;
    if (n >= NTOK) return;

    int slot = 0;
    if (lane < 2) {
        int p = 2*n + lane;
        int e = g_topk_idx[p];
        int pos = atomicAdd(&g_cursor[e], 1);
        slot = g_pstart[e] + pos;
        g_pair_w[slot]   = g_topk_val[p];
        g_slot_tok[slot] = n;
    }
    int slot0 = __shfl_sync(0xffffffffu, slot, 0);
    int slot1 = __shfl_sync(0xffffffffu, slot, 1);

    const float4* xr = (const float4*)(x + (size_t)n*DD);
    __half2* d0 = (__half2*)(g_xg + (size_t)slot0*DD);
    __half2* d1 = (__half2*)(g_xg + (size_t)slot1*DD);
    #pragma unroll
    for (int q = 0; q < 8; q++) {
        float4 v = xr[lane + q*32];
        __half2 a = __floats2half2_rn(v.x, v.y);
        __half2 b = __floats2half2_rn(v.z, v.w);
        d0[2*(lane + q*32)]     = a;
        d0[2*(lane + q*32) + 1] = b;
        d1[2*(lane + q*32)]     = a;
        d1[2*(lane + q*32) + 1] = b;
    }
}

// ---------------- flat fp32->fp16 conversions (side stream) ----------------
__global__ void conv13_kernel(const float* __restrict__ W1, const float* __restrict__ W3) {
    const float* src = blockIdx.z ? W3 : W1;
    __half* dst = blockIdx.z ? g_w3 : g_w1;
    size_t i = ((size_t)blockIdx.x*256 + threadIdx.x)*8;
    float4 v0 = *(const float4*)(src + i);
    float4 v1 = *(const float4*)(src + i + 4);
    __half2 h[4];
    h[0] = __floats2half2_rn(v0.x, v0.y);
    h[1] = __floats2half2_rn(v0.z, v0.w);
    h[2] = __floats2half2_rn(v1.x, v1.y);
    h[3] = __floats2half2_rn(v1.z, v1.w);
    *(uint4*)(dst + i) = *(uint4*)h;
}
__global__ void conv2_kernel(const float* __restrict__ W2) {
    size_t i = ((size_t)blockIdx.x*256 + threadIdx.x)*8;
    float4 v0 = *(const float4*)(W2 + i);
    float4 v1 = *(const float4*)(W2 + i + 4);
    __half2 h[4];
    h[0] = __floats2half2_rn(v0.x, v0.y);
    h[1] = __floats2half2_rn(v0.z, v0.w);
    h[2] = __floats2half2_rn(v1.x, v1.y);
    h[3] = __floats2half2_rn(v1.z, v1.w);
    *(uint4*)(g_w2 + i) = *(uint4*)h;
}

// ============================================================================
// GEMM1 (mma.sync fp16): z1 = X@W1, z3 = X@W3 (trans-B); h = silu(z1+b1)*(z3+b3)
// CTA 128(M)x64(N), BK=32, 4-stage cp.async, 2 CTAs/SM. 8 warps 4(M)x2(N).
// ============================================================================
__global__ void __launch_bounds__(256, 2) gemm1_kernel(const float* __restrict__ b1,
                                                       const float* __restrict__ b3) {
    int e = g_tile_expert[blockIdx.y];
    if (e < 0) return;
    int row0 = blockIdx.y * BM;
    int n0   = blockIdx.x * 64;

    extern __shared__ __align__(1024) char smem[];
    uint32_t sb = smem_u32(smem);

    int tid  = threadIdx.x;
    int lane = tid & 31;
    int wid  = tid >> 5;
    int wm   = wid >> 1;      // 0..3
    int wn   = wid & 1;       // 0..1

    const __half* sA  = g_xg + (size_t)row0*DD;
    const __half* sW1 = g_w1 + (size_t)e*DD*HH + n0;
    const __half* sW3 = g_w3 + (size_t)e*DD*HH + n0;

    #define G1_LOAD(stage, it) do { \
        uint32_t bs = sb + (uint32_t)(stage)*(TILEA + 2*TILEW1); \
        int k0 = (it)*32; \
        _Pragma("unroll") \
        for (int hf = 0; hf < 2; hf++) { \
            int idx = hf*256 + tid; \
            int ar = idx >> 2, ac = idx & 3; \
            cpasync16(bs + (uint32_t)ar*STRA + ac*16, sA + (size_t)ar*DD + k0 + ac*8); \
        } \
        { \
            int wr = tid >> 3, wc = tid & 7; \
            size_t gw = (size_t)(k0 + wr)*HH + wc*8; \
            uint32_t sw = (uint32_t)wr*STRB1 + wc*16; \
            cpasync16(bs + TILEA + sw, sW1 + gw); \
            cpasync16(bs + TILEA + TILEW1 + sw, sW3 + gw); \
        } \
    } while (0)

    float acc1[2][4][4], acc3[2][4][4];
    #pragma unroll
    for (int i = 0; i < 2; i++)
        #pragma unroll
        for (int j = 0; j < 4; j++)
            #pragma unroll
            for (int q = 0; q < 4; q++) { acc1[i][j][q] = 0.f; acc3[i][j][q] = 0.f; }

    int lr = (lane & 7) + 8*((lane >> 3) & 1);
    int lk = (lane >> 4) * 16;
    int bg = lane >> 3, br = lane & 7;
    uint32_t laneB = (uint32_t)((bg & 1)*8 + br)*STRB1 + (uint32_t)(bg >> 1)*16;

    const int NIT = DD/32;   // 32
    G1_LOAD(0, 0); CP_COMMIT();
    G1_LOAD(1, 1); CP_COMMIT();
    G1_LOAD(2, 2); CP_COMMIT();

    for (int it = 0; it < NIT; it++) {
        CP_WAIT2();
        __syncthreads();
        if (it + 3 < NIT) G1_LOAD((it+3)&3, it+3);
        CP_COMMIT();

        uint32_t bs  = sb + (uint32_t)(it&3)*(TILEA + 2*TILEW1);
        uint32_t aA  = bs + (uint32_t)(wm*32 + lr)*STRA + lk;
        uint32_t bW1 = bs + TILEA + laneB + (uint32_t)(wn*32)*2;
        uint32_t bW3 = bW1 + TILEW1;

        #pragma unroll
        for (int h16 = 0; h16 < 2; h16++) {
            uint32_t koA = h16*32;
            uint32_t koB = (uint32_t)(h16*16)*STRB1;
            uint32_t Ah[2][4], b1f[2][4], b3f[2][4];
            #pragma unroll
            for (int mt = 0; mt < 2; mt++)
                ldmx4(Ah[mt], aA + mt*(16*STRA) + koA);
            #pragma unroll
            for (int np = 0; np < 2; np++) {
                ldmx4t(b1f[np], bW1 + koB + np*32);
                ldmx4t(b3f[np], bW3 + koB + np*32);
            }
            #pragma unroll
            for (int np = 0; np < 2; np++)
                #pragma unroll
                for (int s = 0; s < 2; s++) {
                    int nt = np*2 + s;
                    #pragma unroll
                    for (int mt = 0; mt < 2; mt++) {
                        mma16816(acc1[mt][nt], Ah[mt], b1f[np][2*s], b1f[np][2*s+1]);
                        mma16816(acc3[mt][nt], Ah[mt], b3f[np][2*s], b3f[np][2*s+1]);
                    }
                }
        }
    }

    int qrow = lane >> 2, qcol = lane & 3;
    #pragma unroll
    for (int nt = 0; nt < 4; nt++) {
        int col = n0 + wn*32 + nt*8 + qcol*2;
        float2 bb1 = *(const float2*)(b1 + e*HH + col);
        float2 bb3 = *(const float2*)(b3 + e*HH + col);
        #pragma unroll
        for (int mt = 0; mt < 2; mt++) {
            #pragma unroll
            for (int hrow = 0; hrow < 2; hrow++) {
                int r = row0 + wm*32 + mt*16 + qrow + hrow*8;
                float z1a = acc1[mt][nt][2*hrow]   + bb1.x;
                float z1b = acc1[mt][nt][2*hrow+1] + bb1.y;
                float z3a = acc3[mt][nt][2*hrow]   + bb3.x;
                float z3b = acc3[mt][nt][2*hrow+1] + bb3.y;
                float ha = (z1a / (1.f + __expf(-z1a))) * z3a;
                float hb = (z1b / (1.f + __expf(-z1b))) * z3b;
                *reinterpret_cast<__half2*>(g_h + (size_t)r*HH + col) =
                    __floats2half2_rn(ha, hb);
            }
        }
    }
}

// ============================================================================
// GEMM2 (mma.sync fp16): out[tok] += (h @ W2 + b2) * route_w  via red.add.v2
// CTA 128(M)x64(N of D), BK=32, 4-stage, 3 CTAs/SM. 8 warps 4(M)x2(N).
// ============================================================================
__global__ void __launch_bounds__(256, 3) gemm2_kernel(const float* __restrict__ b2,
                                                       float* __restrict__ out) {
    int e = g_tile_expert[blockIdx.y];
    if (e < 0) return;
    int row0 = blockIdx.y * BM;
    int n0   = blockIdx.x * 64;

    extern __shared__ __align__(1024) char smem[];
    uint32_t sb = smem_u32(smem);

    int tid  = threadIdx.x;
    int lane = tid & 31;
    int wid  = tid >> 5;
    int wm   = wid >> 1;      // 0..3
    int wn   = wid & 1;       // 0..1

    const __half* sA = g_h  + (size_t)row0*HH;
    const __half* sW = g_w2 + (size_t)e*HH*DD + n0;

    #define G2_LOAD(stage, it) do { \
        uint32_t bs = sb + (uint32_t)(stage)*(TILEA + TILEW1); \
        int k0 = (it)*32; \
        _Pragma("unroll") \
        for (int hf = 0; hf < 2; hf++) { \
            int idx = hf*256 + tid; \
            int ar = idx >> 2, ac = idx & 3; \
            cpasync16(bs + (uint32_t)ar*STRA + ac*16, sA + (size_t)ar*HH + k0 + ac*8); \
        } \
        { \
            int wr = tid >> 3, wc = tid & 7; \
            cpasync16(bs + TILEA + (uint32_t)wr*STRB1 + wc*16, \
                      sW + (size_t)(k0 + wr)*DD + wc*8); \
        } \
    } while (0)

    float acc[2][4][4];
    #pragma unroll
    for (int i = 0; i < 2; i++)
        #pragma unroll
        for (int j = 0; j < 4; j++)
            #pragma unroll
            for (int q = 0; q < 4; q++) acc[i][j][q] = 0.f;

    int lr = (lane & 7) + 8*((lane >> 3) & 1);
    int lk = (lane >> 4) * 16;
    int bg = lane >> 3, br = lane & 7;
    uint32_t laneB = (uint32_t)((bg & 1)*8 + br)*STRB1 + (uint32_t)(bg >> 1)*16;

    const int NIT = HH/32;   // 64
    G2_LOAD(0, 0); CP_COMMIT();
    G2_LOAD(1, 1); CP_COMMIT();
    G2_LOAD(2, 2); CP_COMMIT();

    for (int it = 0; it < NIT; it++) {
        CP_WAIT2();
        __syncthreads();
        if (it + 3 < NIT) G2_LOAD((it+3)&3, it+3);
        CP_COMMIT();

        uint32_t bs = sb + (uint32_t)(it&3)*(TILEA + TILEW1);
        uint32_t aA = bs + (uint32_t)(wm*32 + lr)*STRA + lk;
        uint32_t bW = bs + TILEA + laneB + (uint32_t)(wn*32)*2;

        #pragma unroll
        for (int h16 = 0; h16 < 2; h16++) {
            uint32_t koA = h16*32;
            uint32_t koB = (uint32_t)(h16*16)*STRB1;
            uint32_t Ah[2][4], bf[2][4];
            #pragma unroll
            for (int mt = 0; mt < 2; mt++)
                ldmx4(Ah[mt], aA + mt*(16*STRA) + koA);
            #pragma unroll
            for (int np = 0; np < 2; np++)
                ldmx4t(bf[np], bW + koB + np*32);
            #pragma unroll
            for (int np = 0; np < 2; np++)
                #pragma unroll
                for (int s = 0; s < 2; s++) {
                    int nt = np*2 + s;
                    #pragma unroll
                    for (int mt = 0; mt < 2; mt++)
                        mma16816(acc[mt][nt], Ah[mt], bf[np][2*s], bf[np][2*s+1]);
                }
        }
    }

    // epilogue: atomically accumulate (acc + b2) * w into out[tok]
    int qrow = lane >> 2, qcol = lane & 3;
    #pragma unroll
    for (int mt = 0; mt < 2; mt++) {
        #pragma unroll
        for (int hrow = 0; hrow < 2; hrow++) {
            int r = row0 + wm*32 + mt*16 + qrow + hrow*8;
            int tok = g_slot_tok[r];
            if (tok < 0) continue;
            float wv = g_pair_w[r];
            float* orow = out + (size_t)tok*DD;
            #pragma unroll
            for (int nt = 0; nt < 4; nt++) {
                int col = n0 + wn*32 + nt*8 + qcol*2;
                float2 bb = *(const float2*)(b2 + e*DD + col);
                redadd2(orow + col,
                        (acc[mt][nt][2*hrow]   + bb.x) * wv,
                        (acc[mt][nt][2*hrow+1] + bb.y) * wv);
            }
        }
    }
}

// ---------------- aux loss (1024 threads, fixed-order reduction) -------------
__global__ void __launch_bounds__(1024) aux_kernel(float* __restrict__ out, int has_aux) {
    __shared__ float red[1024];
    int tid = threadIdx.x;
    int e = tid & 7;
    float p = 0.f;
    for (int n = tid >> 3; n < NTOK; n += 128) p += g_scores[(size_t)n*EE + e];
    red[tid] = p;
    __syncthreads();
    for (int s = 512; s >= 8; s >>= 1) {
        if (tid < s) red[tid] += red[tid + s];
        __syncthreads();
    }
    if (tid == 0 && has_aux) {
        float aux = 0.f;
        for (int ee = 0; ee < EE; ee++) {
            float f = (float)g_counts[ee] / (float)(NTOK*KTOP);
            float P = red[ee] / (float)NTOK;
            aux += f*P;
        }
        out[(size_t)NTOK*DD] = 0.01f * (float)EE * aux;
    }
}

// ---------------- launch (fork-join: conversions + zeroout overlap) ----------
extern "C" void kernel_launch(void* const* d_in, const int* in_sizes, int n_in,
                              void* d_out, int out_size) {
    const float* x  = (const float*)d_in[0];
    const float* Wg = (const float*)d_in[1];
    const float* W1 = (const float*)d_in[2];
    const float* b1 = (const float*)d_in[3];
    const float* W2 = (const float*)d_in[4];
    const float* b2 = (const float*)d_in[5];
    const float* W3 = (const float*)d_in[6];
    const float* b3 = (const float*)d_in[7];
    float* out = (float*)d_out;

    const int G1_SMEM = 4*(TILEA + 2*TILEW1);  // 77824
    const int G2_SMEM = 4*(TILEA + TILEW1);    // 59392
    cudaFuncSetAttribute(gemm1_kernel, cudaFuncAttributeMaxDynamicSharedMemorySize, G1_SMEM);
    cudaFuncSetAttribute(gemm2_kernel, cudaFuncAttributeMaxDynamicSharedMemorySize, G2_SMEM);

    int n4 = out_size/4;
    int ntail = out_size - n4*4;
    int zgrid = (n4 + 255)/256;

    cudaStream_t s2 = 0;
    cudaEvent_t evFork = 0, evW13 = 0, evW2 = 0;
    bool forked = (cudaStreamCreateWithFlags(&s2, cudaStreamNonBlocking) == cudaSuccess)
               && (cudaEventCreateWithFlags(&evFork, cudaEventDisableTiming) == cudaSuccess)
               && (cudaEventCreateWithFlags(&evW13,  cudaEventDisableTiming) == cudaSuccess)
               && (cudaEventCreateWithFlags(&evW2,   cudaEventDisableTiming) == cudaSuccess);

    init_kernel<<<(MAXPAD + 255)/256, 256>>>();

    if (forked) {
        cudaEventRecord(evFork, 0);
        cudaStreamWaitEvent(s2, evFork, 0);
        conv13_kernel<<<dim3((EE*DD*HH)/(256*8), 1, 2), 256, 0, s2>>>(W1, W3);
        cudaEventRecord(evW13, s2);
        zeroout_kernel<<<zgrid, 256, 0, s2>>>(out, n4, ntail);
        conv2_kernel<<<dim3((EE*DD*HH)/(256*8), 1, 1), 256, 0, s2>>>(W2);
        cudaEventRecord(evW2, s2);
    } else {
        conv13_kernel<<<dim3((EE*DD*HH)/(256*8), 1, 2), 256>>>(W1, W3);
        zeroout_kernel<<<zgrid, 256>>>(out, n4, ntail);
        conv2_kernel<<<dim3((EE*DD*HH)/(256*8), 1, 1), 256>>>(W2);
    }

    gate_kernel<<<NTOK/32, 256>>>(x, Wg);
    setup_kernel<<<1, 256>>>();
    assign_gather_kernel<<<NTOK/8, 256>>>(x);

    if (forked) cudaStreamWaitEvent(0, evW13, 0);
    gemm1_kernel<<<dim3(HH/64, MAXTILES), 256, G1_SMEM>>>(b1, b3);
    if (forked) cudaStreamWaitEvent(0, evW2, 0);
    gemm2_kernel<<<dim3(DD/64, MAXTILES), 256, G2_SMEM>>>(b2, out);
    aux_kernel<<<1, 1024>>>(out, out_size > NTOK*DD ? 1 : 0);
}

// round 13
// speedup vs baseline: 1.0114x; 1.0114x over previous
#include <cuda_runtime.h>
#include <cuda_bf16.h>
#include <cuda_fp16.h>
#include <math.h>
#include <stdint.h>

#define DD     1024
#define HH     2048
#define EE     8
#define NTOK   8192
#define KTOP   2
#define NP     (NTOK*KTOP)      // 16384
#define BM     128
#define MAXPAD (NP + EE*BM)     // 17408
#define MAXTILES (MAXPAD/BM)    // 136

#define STRA   80               // A smem row stride (32 fp16 = 64B + 16B pad)
#define TILEA  (128*STRA)       // 10240
#define STRB   272              // GEMM2 B smem row stride (128 fp16 + pad)
#define TILEW  (32*STRB)        // 8704
#define STRB1  144              // GEMM1 B smem row stride (64 fp16 + pad)
#define TILEW1 (32*STRB1)       // 4608
#define NSTG   5                // pipeline stages

// ---------------- device scratch ----------------
__device__ float g_pair_w[MAXPAD];
__device__ int   g_slot_tok[MAXPAD];   // slot -> token (-1 = pad)
__device__ int   g_topk_idx[NP];
__device__ float g_topk_val[NP];
__device__ float g_scores[NTOK*EE];
__device__ int   g_counts[EE];
__device__ int   g_cursor[EE];
__device__ int   g_pstart[EE+1];
__device__ int   g_tile_expert[MAXTILES];

__device__ __align__(16) __half g_xg [(size_t)MAXPAD*DD];      // fp16 x (gathered)
__device__ __align__(16) __half g_w1 [(size_t)EE*DD*HH];       // fp16 W1 [E][D][H]
__device__ __align__(16) __half g_w3 [(size_t)EE*DD*HH];
__device__ __align__(16) __half g_w2 [(size_t)EE*HH*DD];       // fp16 W2 [E][H][D]
__device__ __align__(16) __half g_h  [(size_t)MAXPAD*HH];      // fp16 h

// ---------------- PTX helpers (baseline PTX only) ----------------
__device__ __forceinline__ uint32_t smem_u32(const void* p){
    uint32_t a;
    asm("{ .reg .u64 t; cvta.to.shared.u64 t, %1; cvt.u32.u64 %0, t; }" : "=r"(a) : "l"(p));
    return a;
}
__device__ __forceinline__ void cpasync16(uint32_t dst, const void* src){
    asm volatile("cp.async.cg.shared.global [%0], [%1], 16;" :: "r"(dst), "l"(src));
}
#define CP_COMMIT() asm volatile("cp.async.commit_group;" ::: "memory")
#define CP_WAIT3()  asm volatile("cp.async.wait_group 3;" ::: "memory")

__device__ __forceinline__ void ldmx4(uint32_t (&r)[4], uint32_t addr){
    asm volatile("ldmatrix.sync.aligned.m8n8.x4.shared.b16 {%0,%1,%2,%3}, [%4];"
        : "=r"(r[0]), "=r"(r[1]), "=r"(r[2]), "=r"(r[3]) : "r"(addr));
}
__device__ __forceinline__ void ldmx4t(uint32_t (&r)[4], uint32_t addr){
    asm volatile("ldmatrix.sync.aligned.m8n8.x4.trans.shared.b16 {%0,%1,%2,%3}, [%4];"
        : "=r"(r[0]), "=r"(r[1]), "=r"(r[2]), "=r"(r[3]) : "r"(addr));
}
__device__ __forceinline__ void mma16816(float (&c)[4], const uint32_t (&a)[4],
                                         uint32_t b0, uint32_t b1){
    asm volatile(
        "mma.sync.aligned.m16n8k16.row.col.f32.f16.f16.f32 "
        "{%0,%1,%2,%3}, {%4,%5,%6,%7}, {%8,%9}, {%0,%1,%2,%3};"
        : "+f"(c[0]), "+f"(c[1]), "+f"(c[2]), "+f"(c[3])
        : "r"(a[0]), "r"(a[1]), "r"(a[2]), "r"(a[3]), "r"(b0), "r"(b1));
}
__device__ __forceinline__ void redadd2(float* p, float a, float b){
    asm volatile("red.global.add.v2.f32 [%0], {%1, %2};"
        :: "l"(p), "f"(a), "f"(b) : "memory");
}

// ---------------- init: counters + slot_tok pads ----------------
__global__ void init_kernel() {
    int i = blockIdx.x*blockDim.x + threadIdx.x;
    if (i < MAXPAD) g_slot_tok[i] = -1;
    if (i < EE) { g_counts[i] = 0; g_cursor[i] = 0; }
}

// ---------------- zero the output (side stream) ----------------
__global__ void zeroout_kernel(float* __restrict__ out, int n4, int ntail) {
    int i = blockIdx.x*blockDim.x + threadIdx.x;
    if (i < n4) ((float4*)out)[i] = make_float4(0.f,0.f,0.f,0.f);
    if (i < ntail) out[(size_t)n4*4 + i] = 0.f;
}

// ---------------- gating: 4 tokens per warp, Wg staged once per block --------
__global__ void __launch_bounds__(256) gate_kernel(const float* __restrict__ x,
                                                   const float* __restrict__ Wg) {
    __shared__ float sWg[EE*DD];
    for (int i = threadIdx.x; i < EE*DD/4; i += 256)
        ((float4*)sWg)[i] = ((const float4*)Wg)[i];
    __syncthreads();

    int warp = threadIdx.x >> 5;
    int lane = threadIdx.x & 31;

    for (int t = 0; t < 4; t++) {
        int n = blockIdx.x*32 + warp*4 + t;

        const float4* xr = (const float4*)(x + (size_t)n*DD);
        float4 xv[8];
        #pragma unroll
        for (int q = 0; q < 8; q++) xv[q] = xr[lane + q*32];

        float pr[EE];
        #pragma unroll
        for (int e = 0; e < EE; e++) {
            const float4* wr = (const float4*)(sWg + e*DD);
            float p = 0.f;
            #pragma unroll
            for (int q = 0; q < 8; q++) {
                float4 w = wr[lane + q*32];
                p += xv[q].x*w.x + xv[q].y*w.y + xv[q].z*w.z + xv[q].w*w.w;
            }
            #pragma unroll
            for (int off = 16; off; off >>= 1) p += __shfl_xor_sync(0xffffffffu, p, off);
            pr[e] = p;
        }
        float m = pr[0];
        #pragma unroll
        for (int e = 1; e < EE; e++) m = fmaxf(m, pr[e]);
        float s = 0.f;
        #pragma unroll
        for (int e = 0; e < EE; e++) { pr[e] = __expf(pr[e]-m); s += pr[e]; }
        float inv = 1.f/s;
        #pragma unroll
        for (int e = 0; e < EE; e++) pr[e] *= inv;

        int i1 = 0; float v1 = pr[0];
        #pragma unroll
        for (int e = 1; e < EE; e++) if (pr[e] > v1) { v1 = pr[e]; i1 = e; }
        int i2 = -1; float v2 = -1.f;
        #pragma unroll
        for (int e = 0; e < EE; e++) if (e != i1 && pr[e] > v2) { v2 = pr[e]; i2 = e; }

        if (lane == 0) {
            #pragma unroll
            for (int e = 0; e < EE; e++) g_scores[(size_t)n*EE + e] = pr[e];
            g_topk_idx[2*n]   = i1; g_topk_val[2*n]   = v1;
            g_topk_idx[2*n+1] = i2; g_topk_val[2*n+1] = v2;
            atomicAdd(&g_counts[i1], 1);
            atomicAdd(&g_counts[i2], 1);
        }
    }
}

// ---------------- setup (parallel, 1 block) ----------------
__global__ void setup_kernel() {
    __shared__ int ps[EE+1], cnt[EE];
    int tid = threadIdx.x;
    if (tid == 0) {
        int off = 0;
        for (int e = 0; e < EE; e++) {
            ps[e] = off;
            int c = g_counts[e];
            cnt[e] = c;
            off = (off + c + BM - 1)/BM*BM;
        }
        ps[EE] = off;
    }
    __syncthreads();
    if (tid <= EE) g_pstart[tid] = ps[tid];
    if (tid < MAXTILES) {
        int r0 = tid*BM, e = -1;
        #pragma unroll
        for (int ee = 0; ee < EE; ee++)
            if (r0 >= ps[ee] && r0 < ps[ee] + cnt[ee]) e = ee;
        g_tile_expert[tid] = e;
    }
}

// ---------------- fused assign + gather (one warp per TOKEN) ----------------
__global__ void __launch_bounds__(256) assign_gather_kernel(const float* __restrict__ x) {
    int warp = threadIdx.x >> 5;
    int lane = threadIdx.x & 31;
    int n = blockIdx.x*8 + warp;
    if (n >= NTOK) return;

    int slot = 0;
    if (lane < 2) {
        int p = 2*n + lane;
        int e = g_topk_idx[p];
        int pos = atomicAdd(&g_cursor[e], 1);
        slot = g_pstart[e] + pos;
        g_pair_w[slot]   = g_topk_val[p];
        g_slot_tok[slot] = n;
    }
    int slot0 = __shfl_sync(0xffffffffu, slot, 0);
    int slot1 = __shfl_sync(0xffffffffu, slot, 1);

    const float4* xr = (const float4*)(x + (size_t)n*DD);
    __half2* d0 = (__half2*)(g_xg + (size_t)slot0*DD);
    __half2* d1 = (__half2*)(g_xg + (size_t)slot1*DD);
    #pragma unroll
    for (int q = 0; q < 8; q++) {
        float4 v = xr[lane + q*32];
        __half2 a = __floats2half2_rn(v.x, v.y);
        __half2 b = __floats2half2_rn(v.z, v.w);
        d0[2*(lane + q*32)]     = a;
        d0[2*(lane + q*32) + 1] = b;
        d1[2*(lane + q*32)]     = a;
        d1[2*(lane + q*32) + 1] = b;
    }
}

// ---------------- flat fp32->fp16 conversions (side stream) ----------------
__global__ void conv13_kernel(const float* __restrict__ W1, const float* __restrict__ W3) {
    const float* src = blockIdx.z ? W3 : W1;
    __half* dst = blockIdx.z ? g_w3 : g_w1;
    size_t i = ((size_t)blockIdx.x*256 + threadIdx.x)*8;
    float4 v0 = *(const float4*)(src + i);
    float4 v1 = *(const float4*)(src + i + 4);
    __half2 h[4];
    h[0] = __floats2half2_rn(v0.x, v0.y);
    h[1] = __floats2half2_rn(v0.z, v0.w);
    h[2] = __floats2half2_rn(v1.x, v1.y);
    h[3] = __floats2half2_rn(v1.z, v1.w);
    *(uint4*)(dst + i) = *(uint4*)h;
}
__global__ void conv2_kernel(const float* __restrict__ W2) {
    size_t i = ((size_t)blockIdx.x*256 + threadIdx.x)*8;
    float4 v0 = *(const float4*)(W2 + i);
    float4 v1 = *(const float4*)(W2 + i + 4);
    __half2 h[4];
    h[0] = __floats2half2_rn(v0.x, v0.y);
    h[1] = __floats2half2_rn(v0.z, v0.w);
    h[2] = __floats2half2_rn(v1.x, v1.y);
    h[3] = __floats2half2_rn(v1.z, v1.w);
    *(uint4*)(g_w2 + i) = *(uint4*)h;
}

// ============================================================================
// GEMM1 (mma.sync fp16): z1 = X@W1, z3 = X@W3 (trans-B); h = silu(z1+b1)*(z3+b3)
// CTA 128(M)x64(N), BK=32, 5-stage cp.async, 2 CTAs/SM. 8 warps 4(M)x2(N).
// ============================================================================
__global__ void __launch_bounds__(256, 2) gemm1_kernel(const float* __restrict__ b1,
                                                       const float* __restrict__ b3) {
    int e = g_tile_expert[blockIdx.y];
    if (e < 0) return;
    int row0 = blockIdx.y * BM;
    int n0   = blockIdx.x * 64;

    extern __shared__ __align__(1024) char smem[];
    uint32_t sb = smem_u32(smem);

    int tid  = threadIdx.x;
    int lane = tid & 31;
    int wid  = tid >> 5;
    int wm   = wid >> 1;      // 0..3
    int wn   = wid & 1;       // 0..1

    const __half* sA  = g_xg + (size_t)row0*DD;
    const __half* sW1 = g_w1 + (size_t)e*DD*HH + n0;
    const __half* sW3 = g_w3 + (size_t)e*DD*HH + n0;

    #define G1_LOAD(stage, it) do { \
        uint32_t bs = sb + (uint32_t)(stage)*(TILEA + 2*TILEW1); \
        int k0 = (it)*32; \
        _Pragma("unroll") \
        for (int hf = 0; hf < 2; hf++) { \
            int idx = hf*256 + tid; \
            int ar = idx >> 2, ac = idx & 3; \
            cpasync16(bs + (uint32_t)ar*STRA + ac*16, sA + (size_t)ar*DD + k0 + ac*8); \
        } \
        { \
            int wr = tid >> 3, wc = tid & 7; \
            size_t gw = (size_t)(k0 + wr)*HH + wc*8; \
            uint32_t sw = (uint32_t)wr*STRB1 + wc*16; \
            cpasync16(bs + TILEA + sw, sW1 + gw); \
            cpasync16(bs + TILEA + TILEW1 + sw, sW3 + gw); \
        } \
    } while (0)

    float acc1[2][4][4], acc3[2][4][4];
    #pragma unroll
    for (int i = 0; i < 2; i++)
        #pragma unroll
        for (int j = 0; j < 4; j++)
            #pragma unroll
            for (int q = 0; q < 4; q++) { acc1[i][j][q] = 0.f; acc3[i][j][q] = 0.f; }

    int lr = (lane & 7) + 8*((lane >> 3) & 1);
    int lk = (lane >> 4) * 16;
    int bg = lane >> 3, br = lane & 7;
    uint32_t laneB = (uint32_t)((bg & 1)*8 + br)*STRB1 + (uint32_t)(bg >> 1)*16;

    const int NIT = DD/32;   // 32
    G1_LOAD(0, 0); CP_COMMIT();
    G1_LOAD(1, 1); CP_COMMIT();
    G1_LOAD(2, 2); CP_COMMIT();
    G1_LOAD(3, 3); CP_COMMIT();

    int cur = 0, pf = 4;
    for (int it = 0; it < NIT; it++) {
        CP_WAIT3();
        __syncthreads();
        if (it + 4 < NIT) G1_LOAD(pf, it+4);
        CP_COMMIT();

        uint32_t bs  = sb + (uint32_t)cur*(TILEA + 2*TILEW1);
        uint32_t aA  = bs + (uint32_t)(wm*32 + lr)*STRA + lk;
        uint32_t bW1 = bs + TILEA + laneB + (uint32_t)(wn*32)*2;
        uint32_t bW3 = bW1 + TILEW1;

        #pragma unroll
        for (int h16 = 0; h16 < 2; h16++) {
            uint32_t koA = h16*32;
            uint32_t koB = (uint32_t)(h16*16)*STRB1;
            uint32_t Ah[2][4], b1f[2][4], b3f[2][4];
            #pragma unroll
            for (int mt = 0; mt < 2; mt++)
                ldmx4(Ah[mt], aA + mt*(16*STRA) + koA);
            #pragma unroll
            for (int np = 0; np < 2; np++) {
                ldmx4t(b1f[np], bW1 + koB + np*32);
                ldmx4t(b3f[np], bW3 + koB + np*32);
            }
            #pragma unroll
            for (int np = 0; np < 2; np++)
                #pragma unroll
                for (int s = 0; s < 2; s++) {
                    int nt = np*2 + s;
                    #pragma unroll
                    for (int mt = 0; mt < 2; mt++) {
                        mma16816(acc1[mt][nt], Ah[mt], b1f[np][2*s], b1f[np][2*s+1]);
                        mma16816(acc3[mt][nt], Ah[mt], b3f[np][2*s], b3f[np][2*s+1]);
                    }
                }
        }
        cur = (cur + 1 == NSTG) ? 0 : cur + 1;
        pf  = (pf  + 1 == NSTG) ? 0 : pf  + 1;
    }

    int qrow = lane >> 2, qcol = lane & 3;
    #pragma unroll
    for (int nt = 0; nt < 4; nt++) {
        int col = n0 + wn*32 + nt*8 + qcol*2;
        float2 bb1 = *(const float2*)(b1 + e*HH + col);
        float2 bb3 = *(const float2*)(b3 + e*HH + col);
        #pragma unroll
        for (int mt = 0; mt < 2; mt++) {
            #pragma unroll
            for (int hrow = 0; hrow < 2; hrow++) {
                int r = row0 + wm*32 + mt*16 + qrow + hrow*8;
                float z1a = acc1[mt][nt][2*hrow]   + bb1.x;
                float z1b = acc1[mt][nt][2*hrow+1] + bb1.y;
                float z3a = acc3[mt][nt][2*hrow]   + bb3.x;
                float z3b = acc3[mt][nt][2*hrow+1] + bb3.y;
                float ha = (z1a / (1.f + __expf(-z1a))) * z3a;
                float hb = (z1b / (1.f + __expf(-z1b))) * z3b;
                *reinterpret_cast<__half2*>(g_h + (size_t)r*HH + col) =
                    __floats2half2_rn(ha, hb);
            }
        }
    }
}

// ============================================================================
// GEMM2 (mma.sync fp16): out[tok] += (h @ W2 + b2) * route_w  via red.add.v2
// CTA 128x128, BK=32, 5-stage, 2 CTAs/SM (proven R11 shape), ldsm hoisted.
// ============================================================================
__global__ void __launch_bounds__(256, 2) gemm2_kernel(const float* __restrict__ b2,
                                                       float* __restrict__ out) {
    int e = g_tile_expert[blockIdx.y];
    if (e < 0) return;
    int row0 = blockIdx.y * BM;
    int n0   = blockIdx.x * 128;

    extern __shared__ __align__(1024) char smem[];
    uint32_t sb = smem_u32(smem);

    int tid  = threadIdx.x;
    int lane = tid & 31;
    int wid  = tid >> 5;
    int wm   = wid >> 2;
    int wn   = wid & 3;

    const __half* sA = g_h  + (size_t)row0*HH;
    const __half* sW = g_w2 + (size_t)e*HH*DD + n0;

    #define G2_LOAD(stage, it) do { \
        uint32_t bs = sb + (uint32_t)(stage)*(TILEA + TILEW); \
        int k0 = (it)*32; \
        _Pragma("unroll") \
        for (int hf = 0; hf < 2; hf++) { \
            int idx = hf*256 + tid; \
            int ar = idx >> 2, ac = idx & 3; \
            cpasync16(bs + (uint32_t)ar*STRA + ac*16, sA + (size_t)ar*HH + k0 + ac*8); \
            int wr = idx >> 4, wc = idx & 15; \
            cpasync16(bs + TILEA + (uint32_t)wr*STRB + wc*16, \
                      sW + (size_t)(k0 + wr)*DD + wc*8); \
        } \
    } while (0)

    float acc[4][4][4];
    #pragma unroll
    for (int i = 0; i < 4; i++)
        #pragma unroll
        for (int j = 0; j < 4; j++)
            #pragma unroll
            for (int q = 0; q < 4; q++) acc[i][j][q] = 0.f;

    int lr = (lane & 7) + 8*((lane >> 3) & 1);
    int lk = (lane >> 4) * 16;
    int bg = lane >> 3, br = lane & 7;
    uint32_t laneB = (uint32_t)((bg & 1)*8 + br)*STRB + (uint32_t)(bg >> 1)*16;

    const int NIT = HH/32;   // 64
    G2_LOAD(0, 0); CP_COMMIT();
    G2_LOAD(1, 1); CP_COMMIT();
    G2_LOAD(2, 2); CP_COMMIT();
    G2_LOAD(3, 3); CP_COMMIT();

    int cur = 0, pf = 4;
    for (int it = 0; it < NIT; it++) {
        CP_WAIT3();
        __syncthreads();
        if (it + 4 < NIT) G2_LOAD(pf, it+4);
        CP_COMMIT();

        uint32_t bs = sb + (uint32_t)cur*(TILEA + TILEW);
        uint32_t aA = bs + (uint32_t)(wm*64 + lr)*STRA + lk;
        uint32_t bW = bs + TILEA + laneB + (uint32_t)(wn*32)*2;

        #pragma unroll
        for (int h16 = 0; h16 < 2; h16++) {
            uint32_t koA = h16*32;
            uint32_t koB = (uint32_t)(h16*16)*STRB;
            uint32_t Ah[4][4], bf[2][4];
            #pragma unroll
            for (int mt = 0; mt < 4; mt++)
                ldmx4(Ah[mt], aA + mt*(16*STRA) + koA);
            #pragma unroll
            for (int np = 0; np < 2; np++)
                ldmx4t(bf[np], bW + koB + np*32);
            #pragma unroll
            for (int np = 0; np < 2; np++)
                #pragma unroll
                for (int s = 0; s < 2; s++) {
                    int nt = np*2 + s;
                    #pragma unroll
                    for (int mt = 0; mt < 4; mt++)
                        mma16816(acc[mt][nt], Ah[mt], bf[np][2*s], bf[np][2*s+1]);
                }
        }
        cur = (cur + 1 == NSTG) ? 0 : cur + 1;
        pf  = (pf  + 1 == NSTG) ? 0 : pf  + 1;
    }

    // epilogue: atomically accumulate (acc + b2) * w into out[tok]
    int qrow = lane >> 2, qcol = lane & 3;
    #pragma unroll
    for (int mt = 0; mt < 4; mt++) {
        #pragma unroll
        for (int hrow = 0; hrow < 2; hrow++) {
            int r = row0 + wm*64 + mt*16 + qrow + hrow*8;
            int tok = g_slot_tok[r];
            if (tok < 0) continue;
            float wv = g_pair_w[r];
            float* orow = out + (size_t)tok*DD;
            #pragma unroll
            for (int nt = 0; nt < 4; nt++) {
                int col = n0 + wn*32 + nt*8 + qcol*2;
                float2 bb = *(const float2*)(b2 + e*DD + col);
                redadd2(orow + col,
                        (acc[mt][nt][2*hrow]   + bb.x) * wv,
                        (acc[mt][nt][2*hrow+1] + bb.y) * wv);
            }
        }
    }
}

// ---------------- aux loss (1024 threads, fixed-order reduction) -------------
__global__ void __launch_bounds__(1024) aux_kernel(float* __restrict__ out, int has_aux) {
    __shared__ float red[1024];
    int tid = threadIdx.x;
    int e = tid & 7;
    float p = 0.f;
    for (int n = tid >> 3; n < NTOK; n += 128) p += g_scores[(size_t)n*EE + e];
    red[tid] = p;
    __syncthreads();
    for (int s = 512; s >= 8; s >>= 1) {
        if (tid < s) red[tid] += red[tid + s];
        __syncthreads();
    }
    if (tid == 0 && has_aux) {
        float aux = 0.f;
        for (int ee = 0; ee < EE; ee++) {
            float f = (float)g_counts[ee] / (float)(NTOK*KTOP);
            float P = red[ee] / (float)NTOK;
            aux += f*P;
        }
        out[(size_t)NTOK*DD] = 0.01f * (float)EE * aux;
    }
}

// ---------------- launch (fork-join: conversions + zeroout overlap) ----------
extern "C" void kernel_launch(void* const* d_in, const int* in_sizes, int n_in,
                              void* d_out, int out_size) {
    const float* x  = (const float*)d_in[0];
    const float* Wg = (const float*)d_in[1];
    const float* W1 = (const float*)d_in[2];
    const float* b1 = (const float*)d_in[3];
    const float* W2 = (const float*)d_in[4];
    const float* b2 = (const float*)d_in[5];
    const float* W3 = (const float*)d_in[6];
    const float* b3 = (const float*)d_in[7];
    float* out = (float*)d_out;

    const int G1_SMEM = NSTG*(TILEA + 2*TILEW1);  // 97280
    const int G2_SMEM = NSTG*(TILEA + TILEW);     // 94720
    cudaFuncSetAttribute(gemm1_kernel, cudaFuncAttributeMaxDynamicSharedMemorySize, G1_SMEM);
    cudaFuncSetAttribute(gemm2_kernel, cudaFuncAttributeMaxDynamicSharedMemorySize, G2_SMEM);

    int n4 = out_size/4;
    int ntail = out_size - n4*4;
    int zgrid = (n4 + 255)/256;

    cudaStream_t s2 = 0;
    cudaEvent_t evFork = 0, evW13 = 0, evW2 = 0;
    bool forked = (cudaStreamCreateWithFlags(&s2, cudaStreamNonBlocking) == cudaSuccess)
               && (cudaEventCreateWithFlags(&evFork, cudaEventDisableTiming) == cudaSuccess)
               && (cudaEventCreateWithFlags(&evW13,  cudaEventDisableTiming) == cudaSuccess)
               && (cudaEventCreateWithFlags(&evW2,   cudaEventDisableTiming) == cudaSuccess);

    init_kernel<<<(MAXPAD + 255)/256, 256>>>();

    if (forked) {
        cudaEventRecord(evFork, 0);
        cudaStreamWaitEvent(s2, evFork, 0);
        conv13_kernel<<<dim3((EE*DD*HH)/(256*8), 1, 2), 256, 0, s2>>>(W1, W3);
        cudaEventRecord(evW13, s2);
        zeroout_kernel<<<zgrid, 256, 0, s2>>>(out, n4, ntail);
        conv2_kernel<<<dim3((EE*DD*HH)/(256*8), 1, 1), 256, 0, s2>>>(W2);
        cudaEventRecord(evW2, s2);
    } else {
        conv13_kernel<<<dim3((EE*DD*HH)/(256*8), 1, 2), 256>>>(W1, W3);
        zeroout_kernel<<<zgrid, 256>>>(out, n4, ntail);
        conv2_kernel<<<dim3((EE*DD*HH)/(256*8), 1, 1), 256>>>(W2);
    }

    gate_kernel<<<NTOK/32, 256>>>(x, Wg);
    setup_kernel<<<1, 256>>>();
    assign_gather_kernel<<<NTOK/8, 256>>>(x);

    if (forked) cudaStreamWaitEvent(0, evW13, 0);
    gemm1_kernel<<<dim3(HH/64, MAXTILES), 256, G1_SMEM>>>(b1, b3);
    if (forked) cudaStreamWaitEvent(0, evW2, 0);
    gemm2_kernel<<<dim3(DD/128, MAXTILES), 256, G2_SMEM>>>(b2, out);
    aux_kernel<<<1, 1024>>>(out, out_size > NTOK*DD ? 1 : 0);
}

// round 14
// speedup vs baseline: 1.0320x; 1.0203x over previous
#include <cuda_runtime.h>
#include <cuda_bf16.h>
#include <cuda_fp16.h>
#include <math.h>
#include <stdint.h>

#define DD     1024
#define HH     2048
#define EE     8
#define NTOK   8192
#define KTOP   2
#define NP     (NTOK*KTOP)      // 16384
#define BM     128
#define MAXPAD (NP + EE*BM)     // 17408
#define MAXTILES (MAXPAD/BM)    // 136

#define STRA   80               // A smem row stride (32 fp16 = 64B + 16B pad)
#define TILEA  (128*STRA)       // 10240
#define STRB   272              // GEMM2 B smem row stride (128 fp16 + pad)
#define TILEW  (32*STRB)        // 8704
#define STRB1  144              // GEMM1 B smem row stride (64 fp16 + pad)
#define TILEW1 (32*STRB1)       // 4608

// ---------------- device scratch ----------------
__device__ float g_pair_w[MAXPAD];
__device__ int   g_slot_tok[MAXPAD];   // slot -> token (-1 = pad)
__device__ int   g_topk_idx[NP];
__device__ float g_topk_val[NP];
__device__ float g_scores[NTOK*EE];
__device__ int   g_counts[EE];
__device__ int   g_cursor[EE];
__device__ int   g_pstart[EE+1];
__device__ int   g_tile_expert[MAXTILES];

__device__ __align__(16) __half g_xg [(size_t)MAXPAD*DD];      // fp16 x (gathered)
__device__ __align__(16) __half g_w1 [(size_t)EE*DD*HH];       // fp16 W1 [E][D][H]
__device__ __align__(16) __half g_w3 [(size_t)EE*DD*HH];
__device__ __align__(16) __half g_w2 [(size_t)EE*HH*DD];       // fp16 W2 [E][H][D]
__device__ __align__(16) __half g_h  [(size_t)MAXPAD*HH];      // fp16 h

// ---------------- PTX helpers (baseline PTX only) ----------------
__device__ __forceinline__ uint32_t smem_u32(const void* p){
    uint32_t a;
    asm("{ .reg .u64 t; cvta.to.shared.u64 t, %1; cvt.u32.u64 %0, t; }" : "=r"(a) : "l"(p));
    return a;
}
__device__ __forceinline__ void cpasync16(uint32_t dst, const void* src){
    asm volatile("cp.async.cg.shared.global [%0], [%1], 16;" :: "r"(dst), "l"(src));
}
#define CP_COMMIT() asm volatile("cp.async.commit_group;" ::: "memory")
#define CP_WAIT2()  asm volatile("cp.async.wait_group 2;" ::: "memory")

__device__ __forceinline__ void ldmx4(uint32_t (&r)[4], uint32_t addr){
    asm volatile("ldmatrix.sync.aligned.m8n8.x4.shared.b16 {%0,%1,%2,%3}, [%4];"
        : "=r"(r[0]), "=r"(r[1]), "=r"(r[2]), "=r"(r[3]) : "r"(addr));
}
__device__ __forceinline__ void ldmx4t(uint32_t (&r)[4], uint32_t addr){
    asm volatile("ldmatrix.sync.aligned.m8n8.x4.trans.shared.b16 {%0,%1,%2,%3}, [%4];"
        : "=r"(r[0]), "=r"(r[1]), "=r"(r[2]), "=r"(r[3]) : "r"(addr));
}
__device__ __forceinline__ void mma16816(float (&c)[4], const uint32_t (&a)[4],
                                         uint32_t b0, uint32_t b1){
    asm volatile(
        "mma.sync.aligned.m16n8k16.row.col.f32.f16.f16.f32 "
        "{%0,%1,%2,%3}, {%4,%5,%6,%7}, {%8,%9}, {%0,%1,%2,%3};"
        : "+f"(c[0]), "+f"(c[1]), "+f"(c[2]), "+f"(c[3])
        : "r"(a[0]), "r"(a[1]), "r"(a[2]), "r"(a[3]), "r"(b0), "r"(b1));
}
__device__ __forceinline__ void redadd2(float* p, float a, float b){
    asm volatile("red.global.add.v2.f32 [%0], {%1, %2};"
        :: "l"(p), "f"(a), "f"(b) : "memory");
}

// ---------------- init: counters + slot_tok pads ----------------
__global__ void init_kernel() {
    int i = blockIdx.x*blockDim.x + threadIdx.x;
    if (i < MAXPAD) g_slot_tok[i] = -1;
    if (i < EE) { g_counts[i] = 0; g_cursor[i] = 0; }
}

// ---------------- zero the output (side stream) ----------------
__global__ void zeroout_kernel(float* __restrict__ out, int n4, int ntail) {
    int i = blockIdx.x*blockDim.x + threadIdx.x;
    if (i < n4) ((float4*)out)[i] = make_float4(0.f,0.f,0.f,0.f);
    if (i < ntail) out[(size_t)n4*4 + i] = 0.f;
}

// ---------------- gating: 4 tokens per warp, Wg staged once per block --------
__global__ void __launch_bounds__(256) gate_kernel(const float* __restrict__ x,
                                                   const float* __restrict__ Wg) {
    __shared__ float sWg[EE*DD];
    for (int i = threadIdx.x; i < EE*DD/4; i += 256)
        ((float4*)sWg)[i] = ((const float4*)Wg)[i];
    __syncthreads();

    int warp = threadIdx.x >> 5;
    int lane = threadIdx.x & 31;

    for (int t = 0; t < 4; t++) {
        int n = blockIdx.x*32 + warp*4 + t;

        const float4* xr = (const float4*)(x + (size_t)n*DD);
        float4 xv[8];
        #pragma unroll
        for (int q = 0; q < 8; q++) xv[q] = xr[lane + q*32];

        float pr[EE];
        #pragma unroll
        for (int e = 0; e < EE; e++) {
            const float4* wr = (const float4*)(sWg + e*DD);
            float p = 0.f;
            #pragma unroll
            for (int q = 0; q < 8; q++) {
                float4 w = wr[lane + q*32];
                p += xv[q].x*w.x + xv[q].y*w.y + xv[q].z*w.z + xv[q].w*w.w;
            }
            #pragma unroll
            for (int off = 16; off; off >>= 1) p += __shfl_xor_sync(0xffffffffu, p, off);
            pr[e] = p;
        }
        float m = pr[0];
        #pragma unroll
        for (int e = 1; e < EE; e++) m = fmaxf(m, pr[e]);
        float s = 0.f;
        #pragma unroll
        for (int e = 0; e < EE; e++) { pr[e] = __expf(pr[e]-m); s += pr[e]; }
        float inv = 1.f/s;
        #pragma unroll
        for (int e = 0; e < EE; e++) pr[e] *= inv;

        int i1 = 0; float v1 = pr[0];
        #pragma unroll
        for (int e = 1; e < EE; e++) if (pr[e] > v1) { v1 = pr[e]; i1 = e; }
        int i2 = -1; float v2 = -1.f;
        #pragma unroll
        for (int e = 0; e < EE; e++) if (e != i1 && pr[e] > v2) { v2 = pr[e]; i2 = e; }

        if (lane == 0) {
            #pragma unroll
            for (int e = 0; e < EE; e++) g_scores[(size_t)n*EE + e] = pr[e];
            g_topk_idx[2*n]   = i1; g_topk_val[2*n]   = v1;
            g_topk_idx[2*n+1] = i2; g_topk_val[2*n+1] = v2;
            atomicAdd(&g_counts[i1], 1);
            atomicAdd(&g_counts[i2], 1);
        }
    }
}

// ---------------- setup (parallel, 1 block) ----------------
__global__ void setup_kernel() {
    __shared__ int ps[EE+1], cnt[EE];
    int tid = threadIdx.x;
    if (tid == 0) {
        int off = 0;
        for (int e = 0; e < EE; e++) {
            ps[e] = off;
            int c = g_counts[e];
            cnt[e] = c;
            off = (off + c + BM - 1)/BM*BM;
        }
        ps[EE] = off;
    }
    __syncthreads();
    if (tid <= EE) g_pstart[tid] = ps[tid];
    if (tid < MAXTILES) {
        int r0 = tid*BM, e = -1;
        #pragma unroll
        for (int ee = 0; ee < EE; ee++)
            if (r0 >= ps[ee] && r0 < ps[ee] + cnt[ee]) e = ee;
        g_tile_expert[tid] = e;
    }
}

// ---------------- fused assign + gather (one warp per TOKEN) ----------------
__global__ void __launch_bounds__(256) assign_gather_kernel(const float* __restrict__ x) {
    int warp = threadIdx.x >> 5;
    int lane = threadIdx.x & 31;
    int n = blockIdx.x*8 + warp;
    if (n >= NTOK) return;

    int slot = 0;
    if (lane < 2) {
        int p = 2*n + lane;
        int e = g_topk_idx[p];
        int pos = atomicAdd(&g_cursor[e], 1);
        slot = g_pstart[e] + pos;
        g_pair_w[slot]   = g_topk_val[p];
        g_slot_tok[slot] = n;
    }
    int slot0 = __shfl_sync(0xffffffffu, slot, 0);
    int slot1 = __shfl_sync(0xffffffffu, slot, 1);

    const float4* xr = (const float4*)(x + (size_t)n*DD);
    __half2* d0 = (__half2*)(g_xg + (size_t)slot0*DD);
    __half2* d1 = (__half2*)(g_xg + (size_t)slot1*DD);
    #pragma unroll
    for (int q = 0; q < 8; q++) {
        float4 v = xr[lane + q*32];
        __half2 a = __floats2half2_rn(v.x, v.y);
        __half2 b = __floats2half2_rn(v.z, v.w);
        d0[2*(lane + q*32)]     = a;
        d0[2*(lane + q*32) + 1] = b;
        d1[2*(lane + q*32)]     = a;
        d1[2*(lane + q*32) + 1] = b;
    }
}

// ---------------- flat fp32->fp16 conversions (side stream) ----------------
__global__ void conv13_kernel(const float* __restrict__ W1, const float* __restrict__ W3) {
    const float* src = blockIdx.z ? W3 : W1;
    __half* dst = blockIdx.z ? g_w3 : g_w1;
    size_t i = ((size_t)blockIdx.x*256 + threadIdx.x)*8;
    float4 v0 = *(const float4*)(src + i);
    float4 v1 = *(const float4*)(src + i + 4);
    __half2 h[4];
    h[0] = __floats2half2_rn(v0.x, v0.y);
    h[1] = __floats2half2_rn(v0.z, v0.w);
    h[2] = __floats2half2_rn(v1.x, v1.y);
    h[3] = __floats2half2_rn(v1.z, v1.w);
    *(uint4*)(dst + i) = *(uint4*)h;
}
__global__ void conv2_kernel(const float* __restrict__ W2) {
    size_t i = ((size_t)blockIdx.x*256 + threadIdx.x)*8;
    float4 v0 = *(const float4*)(W2 + i);
    float4 v1 = *(const float4*)(W2 + i + 4);
    __half2 h[4];
    h[0] = __floats2half2_rn(v0.x, v0.y);
    h[1] = __floats2half2_rn(v0.z, v0.w);
    h[2] = __floats2half2_rn(v1.x, v1.y);
    h[3] = __floats2half2_rn(v1.z, v1.w);
    *(uint4*)(g_w2 + i) = *(uint4*)h;
}

// ============================================================================
// GEMM1 (mma.sync fp16): z1 = X@W1, z3 = X@W3 (trans-B); h = silu(z1+b1)*(z3+b3)
// CTA 128(M)x64(N), BK=32, 4-stage cp.async, 2 CTAs/SM. 8 warps 4(M)x2(N).
// ============================================================================
__global__ void __launch_bounds__(256, 2) gemm1_kernel(const float* __restrict__ b1,
                                                       const float* __restrict__ b3) {
    int e = g_tile_expert[blockIdx.y];
    if (e < 0) return;
    int row0 = blockIdx.y * BM;
    int n0   = blockIdx.x * 64;

    extern __shared__ __align__(1024) char smem[];
    uint32_t sb = smem_u32(smem);

    int tid  = threadIdx.x;
    int lane = tid & 31;
    int wid  = tid >> 5;
    int wm   = wid >> 1;      // 0..3
    int wn   = wid & 1;       // 0..1

    const __half* sA  = g_xg + (size_t)row0*DD;
    const __half* sW1 = g_w1 + (size_t)e*DD*HH + n0;
    const __half* sW3 = g_w3 + (size_t)e*DD*HH + n0;

    #define G1_LOAD(stage, it) do { \
        uint32_t bs = sb + (uint32_t)(stage)*(TILEA + 2*TILEW1); \
        int k0 = (it)*32; \
        _Pragma("unroll") \
        for (int hf = 0; hf < 2; hf++) { \
            int idx = hf*256 + tid; \
            int ar = idx >> 2, ac = idx & 3; \
            cpasync16(bs + (uint32_t)ar*STRA + ac*16, sA + (size_t)ar*DD + k0 + ac*8); \
        } \
        { \
            int wr = tid >> 3, wc = tid & 7; \
            size_t gw = (size_t)(k0 + wr)*HH + wc*8; \
            uint32_t sw = (uint32_t)wr*STRB1 + wc*16; \
            cpasync16(bs + TILEA + sw, sW1 + gw); \
            cpasync16(bs + TILEA + TILEW1 + sw, sW3 + gw); \
        } \
    } while (0)

    float acc1[2][4][4], acc3[2][4][4];
    #pragma unroll
    for (int i = 0; i < 2; i++)
        #pragma unroll
        for (int j = 0; j < 4; j++)
            #pragma unroll
            for (int q = 0; q < 4; q++) { acc1[i][j][q] = 0.f; acc3[i][j][q] = 0.f; }

    int lr = (lane & 7) + 8*((lane >> 3) & 1);
    int lk = (lane >> 4) * 16;
    int bg = lane >> 3, br = lane & 7;
    uint32_t laneB = (uint32_t)((bg & 1)*8 + br)*STRB1 + (uint32_t)(bg >> 1)*16;

    const int NIT = DD/32;   // 32
    G1_LOAD(0, 0); CP_COMMIT();
    G1_LOAD(1, 1); CP_COMMIT();
    G1_LOAD(2, 2); CP_COMMIT();

    for (int it = 0; it < NIT; it++) {
        CP_WAIT2();
        __syncthreads();
        if (it + 3 < NIT) G1_LOAD((it+3)&3, it+3);
        CP_COMMIT();

        uint32_t bs  = sb + (uint32_t)(it&3)*(TILEA + 2*TILEW1);
        uint32_t aA  = bs + (uint32_t)(wm*32 + lr)*STRA + lk;
        uint32_t bW1 = bs + TILEA + laneB + (uint32_t)(wn*32)*2;
        uint32_t bW3 = bW1 + TILEW1;

        #pragma unroll
        for (int h16 = 0; h16 < 2; h16++) {
            uint32_t koA = h16*32;
            uint32_t koB = (uint32_t)(h16*16)*STRB1;
            uint32_t Ah[2][4], b1f[2][4], b3f[2][4];
            #pragma unroll
            for (int mt = 0; mt < 2; mt++)
                ldmx4(Ah[mt], aA + mt*(16*STRA) + koA);
            #pragma unroll
            for (int np = 0; np < 2; np++) {
                ldmx4t(b1f[np], bW1 + koB + np*32);
                ldmx4t(b3f[np], bW3 + koB + np*32);
            }
            #pragma unroll
            for (int np = 0; np < 2; np++)
                #pragma unroll
                for (int s = 0; s < 2; s++) {
                    int nt = np*2 + s;
                    #pragma unroll
                    for (int mt = 0; mt < 2; mt++) {
                        mma16816(acc1[mt][nt], Ah[mt], b1f[np][2*s], b1f[np][2*s+1]);
                        mma16816(acc3[mt][nt], Ah[mt], b3f[np][2*s], b3f[np][2*s+1]);
                    }
                }
        }
    }

    int qrow = lane >> 2, qcol = lane & 3;
    #pragma unroll
    for (int nt = 0; nt < 4; nt++) {
        int col = n0 + wn*32 + nt*8 + qcol*2;
        float2 bb1 = *(const float2*)(b1 + e*HH + col);
        float2 bb3 = *(const float2*)(b3 + e*HH + col);
        #pragma unroll
        for (int mt = 0; mt < 2; mt++) {
            #pragma unroll
            for (int hrow = 0; hrow < 2; hrow++) {
                int r = row0 + wm*32 + mt*16 + qrow + hrow*8;
                float z1a = acc1[mt][nt][2*hrow]   + bb1.x;
                float z1b = acc1[mt][nt][2*hrow+1] + bb1.y;
                float z3a = acc3[mt][nt][2*hrow]   + bb3.x;
                float z3b = acc3[mt][nt][2*hrow+1] + bb3.y;
                float ha = (z1a / (1.f + __expf(-z1a))) * z3a;
                float hb = (z1b / (1.f + __expf(-z1b))) * z3b;
                *reinterpret_cast<__half2*>(g_h + (size_t)r*HH + col) =
                    __floats2half2_rn(ha, hb);
            }
        }
    }
}

// ============================================================================
// GEMM2 (mma.sync fp16): out[tok] += (h @ W2 + b2) * route_w  via red.add.v2
// CTA 128x128, BK=32, 4-stage, 2 CTAs/SM, one sync/iter, ldsm hoisted.
// ============================================================================
__global__ void __launch_bounds__(256, 2) gemm2_kernel(const float* __restrict__ b2,
                                                       float* __restrict__ out) {
    int e = g_tile_expert[blockIdx.y];
    if (e < 0) return;
    int row0 = blockIdx.y * BM;
    int n0   = blockIdx.x * 128;

    extern __shared__ __align__(1024) char smem[];
    uint32_t sb = smem_u32(smem);

    int tid  = threadIdx.x;
    int lane = tid & 31;
    int wid  = tid >> 5;
    int wm   = wid >> 2;
    int wn   = wid & 3;

    const __half* sA = g_h  + (size_t)row0*HH;
    const __half* sW = g_w2 + (size_t)e*HH*DD + n0;

    #define G2_LOAD(stage, it) do { \
        uint32_t bs = sb + (uint32_t)(stage)*(TILEA + TILEW); \
        int k0 = (it)*32; \
        _Pragma("unroll") \
        for (int hf = 0; hf < 2; hf++) { \
            int idx = hf*256 + tid; \
            int ar = idx >> 2, ac = idx & 3; \
            cpasync16(bs + (uint32_t)ar*STRA + ac*16, sA + (size_t)ar*HH + k0 + ac*8); \
            int wr = idx >> 4, wc = idx & 15; \
            cpasync16(bs + TILEA + (uint32_t)wr*STRB + wc*16, \
                      sW + (size_t)(k0 + wr)*DD + wc*8); \
        } \
    } while (0)

    float acc[4][4][4];
    #pragma unroll
    for (int i = 0; i < 4; i++)
        #pragma unroll
        for (int j = 0; j < 4; j++)
            #pragma unroll
            for (int q = 0; q < 4; q++) acc[i][j][q] = 0.f;

    int lr = (lane & 7) + 8*((lane >> 3) & 1);
    int lk = (lane >> 4) * 16;
    int bg = lane >> 3, br = lane & 7;
    uint32_t laneB = (uint32_t)((bg & 1)*8 + br)*STRB + (uint32_t)(bg >> 1)*16;

    const int NIT = HH/32;   // 64
    G2_LOAD(0, 0); CP_COMMIT();
    G2_LOAD(1, 1); CP_COMMIT();
    G2_LOAD(2, 2); CP_COMMIT();

    for (int it = 0; it < NIT; it++) {
        CP_WAIT2();
        __syncthreads();
        if (it + 3 < NIT) G2_LOAD((it+3)&3, it+3);
        CP_COMMIT();

        uint32_t bs = sb + (uint32_t)(it&3)*(TILEA + TILEW);
        uint32_t aA = bs + (uint32_t)(wm*64 + lr)*STRA + lk;
        uint32_t bW = bs + TILEA + laneB + (uint32_t)(wn*32)*2;

        #pragma unroll
        for (int h16 = 0; h16 < 2; h16++) {
            uint32_t koA = h16*32;
            uint32_t koB = (uint32_t)(h16*16)*STRB;
            uint32_t Ah[4][4], bf[2][4];
            #pragma unroll
            for (int mt = 0; mt < 4; mt++)
                ldmx4(Ah[mt], aA + mt*(16*STRA) + koA);
            #pragma unroll
            for (int np = 0; np < 2; np++)
                ldmx4t(bf[np], bW + koB + np*32);
            #pragma unroll
            for (int np = 0; np < 2; np++)
                #pragma unroll
                for (int s = 0; s < 2; s++) {
                    int nt = np*2 + s;
                    #pragma unroll
                    for (int mt = 0; mt < 4; mt++)
                        mma16816(acc[mt][nt], Ah[mt], bf[np][2*s], bf[np][2*s+1]);
                }
        }
    }

    // epilogue: atomically accumulate (acc + b2) * w into out[tok]
    int qrow = lane >> 2, qcol = lane & 3;
    #pragma unroll
    for (int mt = 0; mt < 4; mt++) {
        #pragma unroll
        for (int hrow = 0; hrow < 2; hrow++) {
            int r = row0 + wm*64 + mt*16 + qrow + hrow*8;
            int tok = g_slot_tok[r];
            if (tok < 0) continue;
            float wv = g_pair_w[r];
            float* orow = out + (size_t)tok*DD;
            #pragma unroll
            for (int nt = 0; nt < 4; nt++) {
                int col = n0 + wn*32 + nt*8 + qcol*2;
                float2 bb = *(const float2*)(b2 + e*DD + col);
                redadd2(orow + col,
                        (acc[mt][nt][2*hrow]   + bb.x) * wv,
                        (acc[mt][nt][2*hrow+1] + bb.y) * wv);
            }
        }
    }
}

// ---------------- aux loss (1024 threads, fixed-order reduction) -------------
__global__ void __launch_bounds__(1024) aux_kernel(float* __restrict__ out, int has_aux) {
    __shared__ float red[1024];
    int tid = threadIdx.x;
    int e = tid & 7;
    float p = 0.f;
    for (int n = tid >> 3; n < NTOK; n += 128) p += g_scores[(size_t)n*EE + e];
    red[tid] = p;
    __syncthreads();
    for (int s = 512; s >= 8; s >>= 1) {
        if (tid < s) red[tid] += red[tid + s];
        __syncthreads();
    }
    if (tid == 0 && has_aux) {
        float aux = 0.f;
        for (int ee = 0; ee < EE; ee++) {
            float f = (float)g_counts[ee] / (float)(NTOK*KTOP);
            float P = red[ee] / (float)NTOK;
            aux += f*P;
        }
        out[(size_t)NTOK*DD] = 0.01f * (float)EE * aux;
    }
}

// ---------------- launch: side stream carries init/convs/zero/aux ------------
extern "C" void kernel_launch(void* const* d_in, const int* in_sizes, int n_in,
                              void* d_out, int out_size) {
    const float* x  = (const float*)d_in[0];
    const float* Wg = (const float*)d_in[1];
    const float* W1 = (const float*)d_in[2];
    const float* b1 = (const float*)d_in[3];
    const float* W2 = (const float*)d_in[4];
    const float* b2 = (const float*)d_in[5];
    const float* W3 = (const float*)d_in[6];
    const float* b3 = (const float*)d_in[7];
    float* out = (float*)d_out;

    const int G1_SMEM = 4*(TILEA + 2*TILEW1);  // 77824
    const int G2_SMEM = 4*(TILEA + TILEW);     // 75776
    cudaFuncSetAttribute(gemm1_kernel, cudaFuncAttributeMaxDynamicSharedMemorySize, G1_SMEM);
    cudaFuncSetAttribute(gemm2_kernel, cudaFuncAttributeMaxDynamicSharedMemorySize, G2_SMEM);

    int n4 = out_size/4;
    int ntail = out_size - n4*4;
    int zgrid = (n4 + 255)/256;
    int has_aux = (out_size > NTOK*DD) ? 1 : 0;

    cudaStream_t s2 = 0;
    cudaEvent_t evFork = 0, evInit = 0, evGate = 0, evW13 = 0, evW2 = 0, evAux = 0;
    bool forked = (cudaStreamCreateWithFlags(&s2, cudaStreamNonBlocking) == cudaSuccess)
               && (cudaEventCreateWithFlags(&evFork, cudaEventDisableTiming) == cudaSuccess)
               && (cudaEventCreateWithFlags(&evInit, cudaEventDisableTiming) == cudaSuccess)
               && (cudaEventCreateWithFlags(&evGate, cudaEventDisableTiming) == cudaSuccess)
               && (cudaEventCreateWithFlags(&evW13,  cudaEventDisableTiming) == cudaSuccess)
               && (cudaEventCreateWithFlags(&evW2,   cudaEventDisableTiming) == cudaSuccess)
               && (cudaEventCreateWithFlags(&evAux,  cudaEventDisableTiming) == cudaSuccess);

    if (forked) {
        cudaEventRecord(evFork, 0);
        cudaStreamWaitEvent(s2, evFork, 0);
        // side stream: init -> conv13 -> zeroout -> conv2 -> (wait gate) -> aux
        init_kernel<<<(MAXPAD + 255)/256, 256, 0, s2>>>();
        cudaEventRecord(evInit, s2);
        conv13_kernel<<<dim3((EE*DD*HH)/(256*8), 1, 2), 256, 0, s2>>>(W1, W3);
        cudaEventRecord(evW13, s2);
        zeroout_kernel<<<zgrid, 256, 0, s2>>>(out, n4, ntail);
        conv2_kernel<<<dim3((EE*DD*HH)/(256*8), 1, 1), 256, 0, s2>>>(W2);
        cudaEventRecord(evW2, s2);

        // main: gate -> setup -> (wait init) -> assign_gather -> gemms
        gate_kernel<<<NTOK/32, 256>>>(x, Wg);
        cudaEventRecord(evGate, 0);
        cudaStreamWaitEvent(s2, evGate, 0);
        aux_kernel<<<1, 1024, 0, s2>>>(out, has_aux);
        cudaEventRecord(evAux, s2);

        setup_kernel<<<1, 256>>>();
        cudaStreamWaitEvent(0, evInit, 0);
        assign_gather_kernel<<<NTOK/8, 256>>>(x);

        cudaStreamWaitEvent(0, evW13, 0);
        gemm1_kernel<<<dim3(HH/64, MAXTILES), 256, G1_SMEM>>>(b1, b3);
        cudaStreamWaitEvent(0, evW2, 0);
        gemm2_kernel<<<dim3(DD/128, MAXTILES), 256, G2_SMEM>>>(b2, out);
        cudaStreamWaitEvent(0, evAux, 0);
    } else {
        init_kernel<<<(MAXPAD + 255)/256, 256>>>();
        conv13_kernel<<<dim3((EE*DD*HH)/(256*8), 1, 2), 256>>>(W1, W3);
        zeroout_kernel<<<zgrid, 256>>>(out, n4, ntail);
        conv2_kernel<<<dim3((EE*DD*HH)/(256*8), 1, 1), 256>>>(W2);
        gate_kernel<<<NTOK/32, 256>>>(x, Wg);
        setup_kernel<<<1, 256>>>();
        assign_gather_kernel<<<NTOK/8, 256>>>(x);
        gemm1_kernel<<<dim3(HH/64, MAXTILES), 256, G1_SMEM>>>(b1, b3);
        gemm2_kernel<<<dim3(DD/128, MAXTILES), 256, G2_SMEM>>>(b2, out);
        aux_kernel<<<1, 1024>>>(out, has_aux);
    }
}